// round 15
// baseline (speedup 1.0000x reference)
#include <cuda_runtime.h>
#include <math.h>

// NFFT operator config: N=(256,256), n=(512,512), m=4, sigma=2
#define NX      512
#define NN      256
#define MW      4
#define PI_F    3.14159265358979f
#define TWO_PI_F 6.283185307179586f
#define BC_W    4.712388980384690f   // (2 - 1/sigma)*pi = 1.5*pi

#define MAX_IMG 16

// Scratch — symbols only, referenced exclusively inside device code
// (host-passed symbol addresses resolve to the host shadow under GB300 ATS).
__device__ float2 d_A [MAX_IMG*NX*NX];   // fftshift(pad(f_hat/phi_hat)) [img][u][v]
__device__ float2 d_Bt[MAX_IMG*NX*NX];   // after FFT over v, transposed [img][k2][u]
__device__ float2 d_G [MAX_IMG*NX*NX/2]; // REAL spectrum, C=2 pack: [b][k1][k2]=(re0,re1)

// ---------------------------------------------------------------------------
// I0 for x >= 3.75 (A&S 9.8.2), rel err ~2e-7
__device__ __forceinline__ float bessel_i0_large(float x) {
    float t = 3.75f / x;
    float p = 0.39894228f + t*(0.01328592f + t*(0.00225319f + t*(-0.00157565f +
              t*(0.00916281f + t*(-0.02057706f + t*(0.02635537f +
              t*(-0.01647633f + t*0.00392377f)))))));
    return expf(x) * rsqrtf(x) * p;
}

// ---------------------------------------------------------------------------
// Folded prep: d_A = fftshift(pad(f_hat/phi_hat))  (proven == literal, R8==R14)
__global__ void prep_kernel(const float* __restrict__ fr, const float* __restrict__ fi,
                            int nimg) {
    int idx = blockIdx.x * blockDim.x + threadIdx.x;
    if (idx >= nimg*NX*NX) return;
    int v   = idx & (NX-1);
    int u   = (idx >> 9) & (NX-1);
    int img = idx >> 18;
    int a = (u + 128) & (NX-1);
    int b = (v + 128) & (NX-1);
    float2 val = make_float2(0.f, 0.f);
    if (a < NN && b < NN) {
        int src = img*NN*NN + a*NN + b;
        float xa = (TWO_PI_F * (float)(a - 128)) / (float)NX;
        float xb = (TWO_PI_F * (float)(b - 128)) / (float)NX;
        float za = MW * sqrtf(BC_W*BC_W - xa*xa);
        float zb = MW * sqrtf(BC_W*BC_W - xb*xb);
        float ph = bessel_i0_large(za) * bessel_i0_large(zb);
        val.x = fr[src] / ph;
        val.y = fi[src] / ph;
    }
    d_A[idx] = val;
}

// ---------------------------------------------------------------------------
// 512-point forward FFT (DIF Stockham, radix-2), 128 threads. Proven correct
// (produces values identical to the definitional DFT — R8 == R14).
__device__ __forceinline__ float2* fft512(float2* s0, float2* s1) {
    float2* x = s0;
    float2* y = s1;
    int l = 256;
    #pragma unroll
    for (int p = 0; p < 9; ++p) {
        int m = 1 << p;
        #pragma unroll
        for (int it = 0; it < 2; ++it) {
            int idx = threadIdx.x + it*128;
            int j   = idx >> p;
            float2 c0 = x[idx];
            float2 c1 = x[idx + 256];
            float ang = -PI_F * (float)j / (float)l;
            float wi, wr;
            __sincosf(ang, &wi, &wr);
            float dx = c0.x - c1.x, dy = c0.y - c1.y;
            int o = idx + j*m;
            y[o]     = make_float2(c0.x + c1.x, c0.y + c1.y);
            y[o + m] = make_float2(dx*wr - dy*wi, dx*wi + dy*wr);
        }
        __syncthreads();
        float2* t = x; x = y; y = t;
        l >>= 1;
    }
    return x;
}

// Pass 1: FFT over v, write transposed -> d_Bt[img][k2][u]
__global__ void fft_pass1(void) {
    __shared__ float2 sbuf[1024];
    int row = blockIdx.x;
    int img = row >> 9, u = row & (NX-1);
    const float2* in = d_A + ((size_t)img << 18) + ((size_t)u << 9);
    for (int i = threadIdx.x; i < NX; i += 128) sbuf[i] = in[i];
    __syncthreads();
    float2* r = fft512(sbuf, sbuf + 512);
    float2* outp = d_Bt + ((size_t)img << 18);
    for (int i = threadIdx.x; i < NX; i += 128) outp[((size_t)i << 9) + u] = r[i];
}

// Pass 2: FFT over u; store ONLY the real part, channel-interleaved:
// ((float*)d_G)[((b*512 + k1)*512 + k2)*C + c] = Re ghat_s[k1][k2]
__global__ void fft_pass2(int C) {
    __shared__ float2 sbuf[1024];
    int row = blockIdx.x;                  // img*512 + k2
    int img = row >> 9, k2 = row & (NX-1);
    int b = img / C, c = img % C;
    const float2* in = d_Bt + ((size_t)img << 18) + ((size_t)k2 << 9);
    for (int i = threadIdx.x; i < NX; i += 128) sbuf[i] = in[i];
    __syncthreads();
    float2* r = fft512(sbuf, sbuf + 512);
    float* outp = (float*)d_G;
    for (int i = threadIdx.x; i < NX; i += 128)
        outp[(((size_t)(b*NX + i) << 9) + k2)*C + c] = r[i].x;
}

// ---------------------------------------------------------------------------
// Separable 8x8 Kaiser-Bessel weights; folded index i = (base+j) & 511
// (identical to literal (base+j+256)&511 read of the ifftshifted grid).
__device__ __forceinline__ void kb_setup(float x0, float x1,
                                         float* w0, float* w1, int* i0, int* i1) {
    float fx0 = x0 * (float)NX;
    float fx1 = x1 * (float)NX;
    int base0 = (int)ceilf(fx0) - MW;
    int base1 = (int)ceilf(fx1) - MW;
    float dd0 = fx0 - (float)base0;
    float dd1 = fx1 - (float)base1;
    #pragma unroll
    for (int j = 0; j < 8; ++j) {
        float u0 = dd0 - (float)j;
        float t0 = (float)(MW*MW) - u0*u0;
        if (t0 > 0.f) { float s = sqrtf(t0); w0[j] = sinhf(BC_W*s) / (s*PI_F); }
        else w0[j] = 0.f;
        float u1 = dd1 - (float)j;
        float t1 = (float)(MW*MW) - u1*u1;
        if (t1 > 0.f) { float s = sqrtf(t1); w1[j] = sinhf(BC_W*s) / (s*PI_F); }
        else w1[j] = 0.f;
        i0[j] = (base0 + j) & (NX-1);
        i1[j] = (base1 + j) & (NX-1);
    }
}

// C==2 fast path. One float2 load per tap (re of both channels).
// Output: REAL (B,C,M): out[(b*2+c)*Mn + mi].
__global__ void gather2_kernel(const float* __restrict__ xpts, float* __restrict__ out,
                               int Mn, int limit, long long out_cap) {
    int pid = blockIdx.x * blockDim.x + threadIdx.x;
    if (pid >= limit) return;
    int b  = pid / Mn;
    int mi = pid - b*Mn;

    float w0[8], w1[8];
    int   i0[8], i1[8];
    kb_setup(xpts[2*pid], xpts[2*pid + 1], w0, w1, i0, i1);

    float a0 = 0.f, a1 = 0.f;
    const float2* Gb = d_G + ((size_t)b << 18);
    #pragma unroll
    for (int j0 = 0; j0 < 8; ++j0) {
        const float2* rowp = Gb + ((size_t)i0[j0] << 9);
        float wx = w0[j0];
        #pragma unroll
        for (int j1 = 0; j1 < 8; ++j1) {
            float2 g = __ldg(&rowp[i1[j1]]);
            float wt = wx * w1[j1];
            a0 += wt * g.x;
            a1 += wt * g.y;
        }
    }
    long long q0 = (long long)(b*2 + 0)*Mn + mi;
    long long q1 = (long long)(b*2 + 1)*Mn + mi;
    if (q0 < out_cap) out[q0] = a0;
    if (q1 < out_cap) out[q1] = a1;
}

// Generic path: runtime C (<= 8), real output (B,C,M).
__global__ void gatherN_kernel(const float* __restrict__ xpts, float* __restrict__ out,
                               int Mn, int C, int limit, long long out_cap) {
    int pid = blockIdx.x * blockDim.x + threadIdx.x;
    if (pid >= limit) return;
    int b  = pid / Mn;
    int mi = pid - b*Mn;

    float w0[8], w1[8];
    int   i0[8], i1[8];
    kb_setup(xpts[2*pid], xpts[2*pid + 1], w0, w1, i0, i1);

    float acc[8];
    #pragma unroll
    for (int k = 0; k < 8; ++k) acc[k] = 0.f;

    const float* Gb = (const float*)d_G + (size_t)b*NX*NX*C;
    for (int j0 = 0; j0 < 8; ++j0) {
        const float* rowp = Gb + (size_t)i0[j0]*NX*C;
        float wx = w0[j0];
        for (int j1 = 0; j1 < 8; ++j1) {
            float wt = wx * w1[j1];
            const float* cell = rowp + (size_t)i1[j1]*C;
            for (int c = 0; c < C && c < 8; ++c)
                acc[c] += wt * __ldg(&cell[c]);
        }
    }
    for (int c = 0; c < C && c < 8; ++c) {
        long long q = (long long)(b*C + c)*Mn + mi;
        if (q < out_cap) out[q] = acc[c];
    }
}

// ---------------------------------------------------------------------------
extern "C" void kernel_launch(void* const* d_in, const int* in_sizes, int n_in,
                              void* d_out, int out_size) {
    // Input order (confirmed): (x, f_hat_real, f_hat_imag); x unique-sized.
    long long s0 = in_sizes[0], s1 = (n_in > 1) ? in_sizes[1] : 0,
              s2 = (n_in > 2) ? in_sizes[2] : 0;
    int ix, ir, ii;
    if (s1 == s2)      { ix = 0; ir = 1; ii = 2; }
    else if (s0 == s1) { ir = 0; ii = 1; ix = 2; }
    else               { ir = 0; ix = 1; ii = 2; }
    const float* x  = (const float*)d_in[ix];
    const float* fr = (const float*)d_in[ir];
    const float* fi = (const float*)d_in[ii];
    long long sx = in_sizes[ix];
    long long sf = in_sizes[ir];
    float* out = (float*)d_out;

    // Derived world (proven by R4/R5/R6/R8/R13/R14 jointly):
    //   sx = 2*B*M, sf = B*C*65536, out_size = B*C*M (REAL float32 output).
    // Actuals: B=2, C=2, M=200000, out_size=800000.
    long long BM  = sx / 2;
    long long BCv = sf / (NN*NN);
    int B = 1; long long C = (BCv > 0) ? BCv : 1; long long Mn = BM;
    bool ok = false;
    if (BCv > 0 && out_size > 0) {
        long long num = BCv * BM;                  // out_size = B*C*M (primary)
        if (num % out_size == 0) {
            long long Bd = num / out_size;
            if (Bd >= 1 && BM % Bd == 0 && BCv % Bd == 0 && BCv <= MAX_IMG) {
                B = (int)Bd; C = BCv / Bd; Mn = BM / Bd; ok = true;
            }
        }
        if (!ok) {                                 // fallback: float-pair count
            long long num2 = 2 * num;
            if (num2 % out_size == 0) {
                long long Bd = num2 / out_size;
                if (Bd >= 1 && BM % Bd == 0 && BCv % Bd == 0 && BCv <= MAX_IMG) {
                    B = (int)Bd; C = BCv / Bd; Mn = BM / Bd; ok = true;
                }
            }
        }
    }
    int nimg = (int)BCv;
    if (nimg < 1) nimg = 1;
    if (nimg > MAX_IMG) nimg = MAX_IMG;

    // Pipeline: prep(folded fftshift) -> FFT v -> FFT u (store Re only) -> gather
    prep_kernel<<<(nimg*NX*NX + 255)/256, 256>>>(fr, fi, nimg);
    fft_pass1<<<nimg*NX, 128>>>();
    fft_pass2<<<nimg*NX, 128>>>((int)C);

    long long out_cap = (long long)out_size;
    int limit = (int)(B * Mn);
    int blocks = (limit + 255) / 256;
    if (C == 2) gather2_kernel<<<blocks, 256>>>(x, out, (int)Mn, limit, out_cap);
    else        gatherN_kernel<<<blocks, 256>>>(x, out, (int)Mn, (int)C, limit, out_cap);
}

// round 16
// speedup vs baseline: 1.1995x; 1.1995x over previous
#include <cuda_runtime.h>
#include <math.h>

// NFFT operator config: N=(256,256), n=(512,512), m=4, sigma=2
#define NX      512
#define NN      256
#define MW      4
#define PI_F    3.14159265358979f
#define TWO_PI_F 6.283185307179586f
#define BC_W    4.712388980384690f   // (2 - 1/sigma)*pi = 1.5*pi

#define MAX_IMG 16
#define PAD     520                  // padded grid edge (512 + 8)
#define PADC    260                  // float4 cells per padded row (C=2)
#define PADB    135200               // float4 cells per batch = 520*520/2

// Scratch — symbols only, referenced exclusively inside device code
// (host-passed symbol addresses resolve to the host shadow under GB300 ATS).
__device__ float2 d_Bt[MAX_IMG*NX*NX];     // after FFT over v, transposed [img][k2][u]
                                           // zero columns rely on static zero-init
__device__ float4 d_G4[8*PADB + 64];       // C==2: padded real spectrum, cell=(re0,re1)
                                           // generic C: unpadded layout (fits: 1.05M<=1.08M)

// ---------------------------------------------------------------------------
// I0 for x >= 3.75 (A&S 9.8.2), rel err ~2e-7
__device__ __forceinline__ float bessel_i0_large(float x) {
    float t = 3.75f / x;
    float p = 0.39894228f + t*(0.01328592f + t*(0.00225319f + t*(-0.00157565f +
              t*(0.00916281f + t*(-0.02057706f + t*(0.02635537f +
              t*(-0.01647633f + t*0.00392377f)))))));
    return expf(x) * rsqrtf(x) * p;
}

// ---------------------------------------------------------------------------
// 512-point forward FFT (DIF Stockham, radix-2), 128 threads. Proven correct.
__device__ __forceinline__ float2* fft512(float2* s0, float2* s1) {
    float2* x = s0;
    float2* y = s1;
    int l = 256;
    #pragma unroll
    for (int p = 0; p < 9; ++p) {
        int m = 1 << p;
        #pragma unroll
        for (int it = 0; it < 2; ++it) {
            int idx = threadIdx.x + it*128;
            int j   = idx >> p;
            float2 c0 = x[idx];
            float2 c1 = x[idx + 256];
            float ang = -PI_F * (float)j / (float)l;
            float wi, wr;
            __sincosf(ang, &wi, &wr);
            float dx = c0.x - c1.x, dy = c0.y - c1.y;
            int o = idx + j*m;
            y[o]     = make_float2(c0.x + c1.x, c0.y + c1.y);
            y[o + m] = make_float2(dx*wr - dy*wi, dx*wi + dy*wr);
        }
        __syncthreads();
        float2* t = x; x = y; y = t;
        l >>= 1;
    }
    return x;
}

// Pass 1 (fused prep): only the 256 nonzero rows per image are launched.
// Row u = (ui+384)&511 carries f_hat row a=ui after fftshift(pad(.)).
// Deconvolve by phi_hat on load, FFT over v, write transposed d_Bt[img][k2][u].
// Zero rows of the padded spectrum => zero columns u of d_Bt: never written,
// stay zero from static initialization (deterministic: nothing else writes d_Bt).
__global__ void fft_pass1f(const float* __restrict__ fr, const float* __restrict__ fi) {
    __shared__ float2 sbuf[1024];
    int blk = blockIdx.x;
    int img = blk >> 8, ui = blk & 255;          // ui = f_hat row a
    int u = (ui + 384) & (NX-1);                 // padded-grid row
    float xa = (TWO_PI_F * (float)(ui - 128)) / (float)NX;
    float i0a = bessel_i0_large(MW * sqrtf(BC_W*BC_W - xa*xa));
    for (int i = threadIdx.x; i < NX; i += 128) {
        int bcol = (i + 128) & (NX-1);
        float2 val = make_float2(0.f, 0.f);
        if (bcol < NN) {
            int src = img*NN*NN + ui*NN + bcol;
            float xb = (TWO_PI_F * (float)(bcol - 128)) / (float)NX;
            float i0b = bessel_i0_large(MW * sqrtf(BC_W*BC_W - xb*xb));
            float inv = 1.0f / (i0a * i0b);
            val.x = fr[src] * inv;
            val.y = fi[src] * inv;
        }
        sbuf[i] = val;
    }
    __syncthreads();
    float2* r = fft512(sbuf, sbuf + 512);
    float2* outp = d_Bt + ((size_t)img << 18);
    for (int i = threadIdx.x; i < NX; i += 128) outp[((size_t)i << 9) + u] = r[i];
}

// Pass 2 (C==2, padded): FFT over u; store Re only into the padded 520x520 grid,
// cell (k1,k2) = (re_c0, re_c1); wrap rows/cols <8 replicated at +512.
__global__ void fft_pass2p(void) {
    __shared__ float2 sbuf[1024];
    int row = blockIdx.x;                  // img*512 + k2
    int img = row >> 9, k2 = row & (NX-1);
    int b = img >> 1, c = img & 1;
    const float2* in = d_Bt + ((size_t)img << 18) + ((size_t)k2 << 9);
    for (int i = threadIdx.x; i < NX; i += 128) sbuf[i] = in[i];
    __syncthreads();
    float2* r = fft512(sbuf, sbuf + 512);
    float* outp = (float*)d_G4;
    size_t gb = (size_t)b * (PAD*PAD);
    bool ce = (k2 < 8);
    for (int i = threadIdx.x; i < NX; i += 128) {
        float vre = r[i].x;
        size_t cell = gb + (size_t)i*PAD + k2;
        outp[cell*2 + c] = vre;
        if (ce) outp[(cell + 512)*2 + c] = vre;
        if (i < 8) {
            size_t cell2 = cell + (size_t)512*PAD;
            outp[cell2*2 + c] = vre;
            if (ce) outp[(cell2 + 512)*2 + c] = vre;
        }
    }
}

// Pass 2 (generic C, unpadded): ((float*)d_G4)[((b*512+k1)*512+k2)*C + c] = Re
__global__ void fft_pass2g(int C) {
    __shared__ float2 sbuf[1024];
    int row = blockIdx.x;
    int img = row >> 9, k2 = row & (NX-1);
    int b = img / C, c = img % C;
    const float2* in = d_Bt + ((size_t)img << 18) + ((size_t)k2 << 9);
    for (int i = threadIdx.x; i < NX; i += 128) sbuf[i] = in[i];
    __syncthreads();
    float2* r = fft512(sbuf, sbuf + 512);
    float* outp = (float*)d_G4;
    for (int i = threadIdx.x; i < NX; i += 128)
        outp[(((size_t)(b*NX + i) << 9) + k2)*C + c] = r[i].x;
}

// ---------------------------------------------------------------------------
// Separable 8x8 Kaiser-Bessel weights (indices handled by caller).
__device__ __forceinline__ void kb_weights(float dd, float* w) {
    #pragma unroll
    for (int j = 0; j < 8; ++j) {
        float u = dd - (float)j;
        float t = (float)(MW*MW) - u*u;
        if (t > 0.f) { float s = sqrtf(t); w[j] = sinhf(BC_W*s) / (s*PI_F); }
        else w[j] = 0.f;
    }
}

// C==2 fast path on the padded grid: per row, 5 aligned float4 loads cover the
// 8 contiguous taps (start col rounded down to even; shifted 10-wide weights).
// Output: REAL (B,C,M): out[(b*2+c)*Mn + mi].
__global__ void gather2p_kernel(const float* __restrict__ xpts, float* __restrict__ out,
                                int Mn, int limit, long long out_cap) {
    int pid = blockIdx.x * blockDim.x + threadIdx.x;
    if (pid >= limit) return;
    int b  = pid / Mn;
    int mi = pid - b*Mn;

    float fx0 = xpts[2*pid + 0] * (float)NX;
    float fx1 = xpts[2*pid + 1] * (float)NX;
    int base0 = (int)ceilf(fx0) - MW;
    int base1 = (int)ceilf(fx1) - MW;
    float dd0 = fx0 - (float)base0;
    float dd1 = fx1 - (float)base1;

    float w0[8], w1[8];
    kb_weights(dd0, w0);
    kb_weights(dd1, w1);

    int r0  = base0 & (NX-1);          // padded rows r0..r0+7 <= 518 < 520
    int c1  = base1 & (NX-1);
    int s   = c1 & ~1;                 // even start col, s..s+9 <= 519 < 520
    int odd = c1 & 1;
    float w1e[10];
    #pragma unroll
    for (int t = 0; t < 10; ++t) {
        int j = t - odd;
        w1e[t] = (j >= 0 && j < 8) ? w1[j] : 0.f;
    }

    float a0 = 0.f, a1 = 0.f;
    const float4* Gb = d_G4 + (size_t)b*PADB + (s >> 1);
    #pragma unroll
    for (int j0 = 0; j0 < 8; ++j0) {
        const float4* rp = Gb + (size_t)(r0 + j0)*PADC;
        float wx = w0[j0];
        float s0 = 0.f, s1 = 0.f;
        #pragma unroll
        for (int t = 0; t < 5; ++t) {
            float4 g = __ldg(&rp[t]);       // (re0[2t], re1[2t], re0[2t+1], re1[2t+1])
            s0 += w1e[2*t]*g.x + w1e[2*t+1]*g.z;
            s1 += w1e[2*t]*g.y + w1e[2*t+1]*g.w;
        }
        a0 += wx * s0;
        a1 += wx * s1;
    }
    long long q0 = (long long)(b*2 + 0)*Mn + mi;
    long long q1 = (long long)(b*2 + 1)*Mn + mi;
    if (q0 < out_cap) out[q0] = a0;
    if (q1 < out_cap) out[q1] = a1;
}

// Generic path: runtime C (<= 8), unpadded layout, real output (B,C,M).
__global__ void gatherN_kernel(const float* __restrict__ xpts, float* __restrict__ out,
                               int Mn, int C, int limit, long long out_cap) {
    int pid = blockIdx.x * blockDim.x + threadIdx.x;
    if (pid >= limit) return;
    int b  = pid / Mn;
    int mi = pid - b*Mn;

    float fx0 = xpts[2*pid + 0] * (float)NX;
    float fx1 = xpts[2*pid + 1] * (float)NX;
    int base0 = (int)ceilf(fx0) - MW;
    int base1 = (int)ceilf(fx1) - MW;
    float w0[8], w1[8];
    kb_weights(fx0 - (float)base0, w0);
    kb_weights(fx1 - (float)base1, w1);
    int i0[8], i1[8];
    #pragma unroll
    for (int j = 0; j < 8; ++j) {
        i0[j] = (base0 + j) & (NX-1);
        i1[j] = (base1 + j) & (NX-1);
    }

    float acc[8];
    #pragma unroll
    for (int k = 0; k < 8; ++k) acc[k] = 0.f;

    const float* Gb = (const float*)d_G4 + (size_t)b*NX*NX*C;
    for (int j0 = 0; j0 < 8; ++j0) {
        const float* rowp = Gb + (size_t)i0[j0]*NX*C;
        float wx = w0[j0];
        for (int j1 = 0; j1 < 8; ++j1) {
            float wt = wx * w1[j1];
            const float* cell = rowp + (size_t)i1[j1]*C;
            for (int c = 0; c < C && c < 8; ++c)
                acc[c] += wt * __ldg(&cell[c]);
        }
    }
    for (int c = 0; c < C && c < 8; ++c) {
        long long q = (long long)(b*C + c)*Mn + mi;
        if (q < out_cap) out[q] = acc[c];
    }
}

// ---------------------------------------------------------------------------
extern "C" void kernel_launch(void* const* d_in, const int* in_sizes, int n_in,
                              void* d_out, int out_size) {
    // Input order (confirmed): (x, f_hat_real, f_hat_imag); x unique-sized.
    long long s0 = in_sizes[0], s1 = (n_in > 1) ? in_sizes[1] : 0,
              s2 = (n_in > 2) ? in_sizes[2] : 0;
    int ix, ir, ii;
    if (s1 == s2)      { ix = 0; ir = 1; ii = 2; }
    else if (s0 == s1) { ir = 0; ii = 1; ix = 2; }
    else               { ir = 0; ix = 1; ii = 2; }
    const float* x  = (const float*)d_in[ix];
    const float* fr = (const float*)d_in[ir];
    const float* fi = (const float*)d_in[ii];
    long long sx = in_sizes[ix];
    long long sf = in_sizes[ir];
    float* out = (float*)d_out;

    // World (proven R4..R15): sx=2BM, sf=BC*65536, out_size=B*C*M (REAL fp32).
    // Actuals: B=2, C=2, M=200000.
    long long BM  = sx / 2;
    long long BCv = sf / (NN*NN);
    int B = 1; long long C = (BCv > 0) ? BCv : 1; long long Mn = BM;
    bool ok = false;
    if (BCv > 0 && out_size > 0) {
        long long num = BCv * BM;
        if (num % out_size == 0) {
            long long Bd = num / out_size;
            if (Bd >= 1 && BM % Bd == 0 && BCv % Bd == 0 && BCv <= MAX_IMG) {
                B = (int)Bd; C = BCv / Bd; Mn = BM / Bd; ok = true;
            }
        }
        if (!ok) {
            long long num2 = 2 * num;
            if (num2 % out_size == 0) {
                long long Bd = num2 / out_size;
                if (Bd >= 1 && BM % Bd == 0 && BCv % Bd == 0 && BCv <= MAX_IMG) {
                    B = (int)Bd; C = BCv / Bd; Mn = BM / Bd; ok = true;
                }
            }
        }
    }
    int nimg = (int)BCv;
    if (nimg < 1) nimg = 1;
    if (nimg > MAX_IMG) nimg = MAX_IMG;

    bool fast2 = (C == 2) && (B <= 8);

    // Pipeline: fused prep+FFT v (nonzero rows only) -> FFT u (Re only) -> gather
    fft_pass1f<<<nimg*256, 128>>>(fr, fi);
    if (fast2) fft_pass2p<<<nimg*NX, 128>>>();
    else       fft_pass2g<<<nimg*NX, 128>>>((int)C);

    long long out_cap = (long long)out_size;
    int limit = (int)(B * Mn);
    int blocks = (limit + 255) / 256;
    if (fast2) gather2p_kernel<<<blocks, 256>>>(x, out, (int)Mn, limit, out_cap);
    else       gatherN_kernel<<<blocks, 256>>>(x, out, (int)Mn, (int)C, limit, out_cap);
}

// round 17
// speedup vs baseline: 1.2483x; 1.0407x over previous
#include <cuda_runtime.h>
#include <math.h>

// NFFT operator config: N=(256,256), n=(512,512), m=4, sigma=2
#define NX      512
#define NN      256
#define MW      4
#define PI_F    3.14159265358979f
#define TWO_PI_F 6.283185307179586f
#define BC_W    4.712388980384690f   // (2 - 1/sigma)*pi = 1.5*pi

#define MAX_IMG 16
#define PAD     520                  // padded grid edge (512 + 8)
#define PADC    260                  // float4 cells per padded row (C=2)
#define ROWF    1040                 // floats per padded row
#define PADB    135200               // float4 cells per batch = 520*520/2

// Scratch — symbols only, referenced exclusively inside device code
// (host-passed symbol addresses resolve to the host shadow under GB300 ATS).
__device__ float2 d_Bt[MAX_IMG*NX*NX];   // FFT over v, transposed [img][k2][u]; zero cols = static init
__device__ float4 d_GA[8*PADB];          // even-pair copy: cell t of row = cols (2t, 2t+1), (re0,re1) each
__device__ float4 d_GB[8*PADB];          // odd-shift copy: cell t of row = cols (2t+1, 2t+2)
                                         // generic C path reuses d_GA unpadded (4.33M >= 4.19M floats)

// ---------------------------------------------------------------------------
// I0 for x >= 3.75 (A&S 9.8.2), rel err ~2e-7
__device__ __forceinline__ float bessel_i0_large(float x) {
    float t = 3.75f / x;
    float p = 0.39894228f + t*(0.01328592f + t*(0.00225319f + t*(-0.00157565f +
              t*(0.00916281f + t*(-0.02057706f + t*(0.02635537f +
              t*(-0.01647633f + t*0.00392377f)))))));
    return expf(x) * rsqrtf(x) * p;
}

// ---------------------------------------------------------------------------
// 512-point forward FFT (DIF Stockham, radix-2), 256 threads, 1 butterfly/thread.
__device__ __forceinline__ float2* fft512_t256(float2* s0, float2* s1) {
    float2* x = s0;
    float2* y = s1;
    int l = 256;
    #pragma unroll
    for (int p = 0; p < 9; ++p) {
        int m = 1 << p;
        int idx = threadIdx.x;               // butterfly id 0..255
        int j   = idx >> p;
        float2 c0 = x[idx];
        float2 c1 = x[idx + 256];
        float ang = -PI_F * (float)j / (float)l;
        float wi, wr;
        __sincosf(ang, &wi, &wr);
        float dx = c0.x - c1.x, dy = c0.y - c1.y;
        int o = idx + j*m;
        y[o]     = make_float2(c0.x + c1.x, c0.y + c1.y);
        y[o + m] = make_float2(dx*wr - dy*wi, dx*wi + dy*wr);
        __syncthreads();
        float2* t = x; x = y; y = t;
        l >>= 1;
    }
    return x;
}

// Pass 1 (fused prep): 256 nonzero rows per image; deconvolve on load; FFT over v;
// write transposed d_Bt[img][k2][u]. Zero columns stay zero from static init.
__global__ void fft_pass1f(const float* __restrict__ fr, const float* __restrict__ fi) {
    __shared__ float2 sbuf[1024];
    int blk = blockIdx.x;
    int img = blk >> 8, ui = blk & 255;          // ui = f_hat row
    int u = (ui + 384) & (NX-1);                 // padded-grid row
    float xa = (TWO_PI_F * (float)(ui - 128)) / (float)NX;
    float i0a = bessel_i0_large(MW * sqrtf(BC_W*BC_W - xa*xa));
    for (int i = threadIdx.x; i < NX; i += 256) {
        int bcol = (i + 128) & (NX-1);
        float2 val = make_float2(0.f, 0.f);
        if (bcol < NN) {
            int src = img*NN*NN + ui*NN + bcol;
            float xb = (TWO_PI_F * (float)(bcol - 128)) / (float)NX;
            float i0b = bessel_i0_large(MW * sqrtf(BC_W*BC_W - xb*xb));
            float inv = 1.0f / (i0a * i0b);
            val.x = fr[src] * inv;
            val.y = fi[src] * inv;
        }
        sbuf[i] = val;
    }
    __syncthreads();
    float2* r = fft512_t256(sbuf, sbuf + 512);
    float2* outp = d_Bt + ((size_t)img << 18);
    for (int i = threadIdx.x; i < NX; i += 256) outp[((size_t)i << 9) + u] = r[i];
}

// Pass 2 (C==2): FFT over u; store Re into BOTH padded copies with wrap replication.
// copyA float index: row*ROWF + 2*col + c ;  copyB: row*ROWF + 2*col - 2 + c (col>=1).
__global__ void fft_pass2p(void) {
    __shared__ float2 sbuf[1024];
    int row = blockIdx.x;                  // img*512 + k2
    int img = row >> 9, k2 = row & (NX-1);
    int b = img >> 1, c = img & 1;
    const float2* in = d_Bt + ((size_t)img << 18) + ((size_t)k2 << 9);
    for (int i = threadIdx.x; i < NX; i += 256) sbuf[i] = in[i];
    __syncthreads();
    float2* r = fft512_t256(sbuf, sbuf + 512);
    float* pa = (float*)d_GA;
    float* pb = (float*)d_GB;
    size_t bb = (size_t)b * PAD;
    bool ce = (k2 < 8);
    for (int i = threadIdx.x; i < NX; i += 256) {
        float v = r[i].x;
        #pragma unroll
        for (int rr = 0; rr < 2; ++rr) {
            int ri = i + rr*512;
            if (rr && i >= 8) break;
            size_t fb = (bb + ri) * ROWF;
            pa[fb + 2*k2 + c] = v;
            if (k2 >= 1) pb[fb + 2*k2 - 2 + c] = v;
            if (ce) {
                int ci = k2 + 512;
                pa[fb + 2*ci + c] = v;
                pb[fb + 2*ci - 2 + c] = v;
            }
        }
    }
}

// Pass 2 (generic C, unpadded into d_GA floats)
__global__ void fft_pass2g(int C) {
    __shared__ float2 sbuf[1024];
    int row = blockIdx.x;
    int img = row >> 9, k2 = row & (NX-1);
    int b = img / C, c = img % C;
    const float2* in = d_Bt + ((size_t)img << 18) + ((size_t)k2 << 9);
    for (int i = threadIdx.x; i < NX; i += 256) sbuf[i] = in[i];
    __syncthreads();
    float2* r = fft512_t256(sbuf, sbuf + 512);
    float* outp = (float*)d_GA;
    for (int i = threadIdx.x; i < NX; i += 256)
        outp[(((size_t)(b*NX + i) << 9) + k2)*C + c] = r[i].x;
}

// ---------------------------------------------------------------------------
__device__ __forceinline__ void kb_weights(float dd, float* w) {
    #pragma unroll
    for (int j = 0; j < 8; ++j) {
        float u = dd - (float)j;
        float t = (float)(MW*MW) - u*u;
        if (t > 0.f) { float s = sqrtf(t); w[j] = sinhf(BC_W*s) / (s*PI_F); }
        else w[j] = 0.f;
    }
}

// C==2 gather: parity-selected copy gives 4 aligned float4 loads per row (32/point).
// Output REAL (B,C,M): out[(b*2+c)*Mn + mi].
__global__ void gather2p_kernel(const float* __restrict__ xpts, float* __restrict__ out,
                                int Mn, int limit, long long out_cap) {
    int pid = blockIdx.x * blockDim.x + threadIdx.x;
    if (pid >= limit) return;
    int b  = pid / Mn;
    int mi = pid - b*Mn;

    float fx0 = xpts[2*pid + 0] * (float)NX;
    float fx1 = xpts[2*pid + 1] * (float)NX;
    int base0 = (int)ceilf(fx0) - MW;
    int base1 = (int)ceilf(fx1) - MW;

    float w0[8], w1[8];
    kb_weights(fx0 - (float)base0, w0);
    kb_weights(fx1 - (float)base1, w1);

    int r0  = base0 & (NX-1);              // rows r0..r0+7 <= 518 < 520
    int c1  = base1 & (NX-1);
    int odd = c1 & 1;
    int k   = (c1 - odd) >> 1;             // starting cell in the chosen copy
    const float4* Gb = (odd ? d_GB : d_GA) + (size_t)b*PADB + k;

    float a0 = 0.f, a1 = 0.f;
    #pragma unroll
    for (int j0 = 0; j0 < 8; ++j0) {
        const float4* rp = Gb + (size_t)(r0 + j0)*PADC;
        float wx = w0[j0];
        float s0 = 0.f, s1 = 0.f;
        #pragma unroll
        for (int t = 0; t < 4; ++t) {
            float4 g = __ldg(&rp[t]);      // cols c1+2t, c1+2t+1; (re0,re1) pairs
            s0 += w1[2*t]*g.x + w1[2*t+1]*g.z;
            s1 += w1[2*t]*g.y + w1[2*t+1]*g.w;
        }
        a0 += wx * s0;
        a1 += wx * s1;
    }
    long long q0 = (long long)(b*2 + 0)*Mn + mi;
    long long q1 = (long long)(b*2 + 1)*Mn + mi;
    if (q0 < out_cap) out[q0] = a0;
    if (q1 < out_cap) out[q1] = a1;
}

// Generic path: runtime C (<= 8), unpadded d_GA, real output (B,C,M).
__global__ void gatherN_kernel(const float* __restrict__ xpts, float* __restrict__ out,
                               int Mn, int C, int limit, long long out_cap) {
    int pid = blockIdx.x * blockDim.x + threadIdx.x;
    if (pid >= limit) return;
    int b  = pid / Mn;
    int mi = pid - b*Mn;

    float fx0 = xpts[2*pid + 0] * (float)NX;
    float fx1 = xpts[2*pid + 1] * (float)NX;
    int base0 = (int)ceilf(fx0) - MW;
    int base1 = (int)ceilf(fx1) - MW;
    float w0[8], w1[8];
    kb_weights(fx0 - (float)base0, w0);
    kb_weights(fx1 - (float)base1, w1);
    int i0[8], i1[8];
    #pragma unroll
    for (int j = 0; j < 8; ++j) {
        i0[j] = (base0 + j) & (NX-1);
        i1[j] = (base1 + j) & (NX-1);
    }

    float acc[8];
    #pragma unroll
    for (int k = 0; k < 8; ++k) acc[k] = 0.f;

    const float* Gb = (const float*)d_GA + (size_t)b*NX*NX*C;
    for (int j0 = 0; j0 < 8; ++j0) {
        const float* rowp = Gb + (size_t)i0[j0]*NX*C;
        float wx = w0[j0];
        for (int j1 = 0; j1 < 8; ++j1) {
            float wt = wx * w1[j1];
            const float* cell = rowp + (size_t)i1[j1]*C;
            for (int c = 0; c < C && c < 8; ++c)
                acc[c] += wt * __ldg(&cell[c]);
        }
    }
    for (int c = 0; c < C && c < 8; ++c) {
        long long q = (long long)(b*C + c)*Mn + mi;
        if (q < out_cap) out[q] = acc[c];
    }
}

// ---------------------------------------------------------------------------
extern "C" void kernel_launch(void* const* d_in, const int* in_sizes, int n_in,
                              void* d_out, int out_size) {
    // Input order (confirmed): (x, f_hat_real, f_hat_imag); x unique-sized.
    long long s0 = in_sizes[0], s1 = (n_in > 1) ? in_sizes[1] : 0,
              s2 = (n_in > 2) ? in_sizes[2] : 0;
    int ix, ir, ii;
    if (s1 == s2)      { ix = 0; ir = 1; ii = 2; }
    else if (s0 == s1) { ir = 0; ii = 1; ix = 2; }
    else               { ir = 0; ix = 1; ii = 2; }
    const float* x  = (const float*)d_in[ix];
    const float* fr = (const float*)d_in[ir];
    const float* fi = (const float*)d_in[ii];
    long long sx = in_sizes[ix];
    long long sf = in_sizes[ir];
    float* out = (float*)d_out;

    // World (proven R4..R15): sx=2BM, sf=BC*65536, out_size=B*C*M (REAL fp32).
    long long BM  = sx / 2;
    long long BCv = sf / (NN*NN);
    int B = 1; long long C = (BCv > 0) ? BCv : 1; long long Mn = BM;
    bool ok = false;
    if (BCv > 0 && out_size > 0) {
        long long num = BCv * BM;
        if (num % out_size == 0) {
            long long Bd = num / out_size;
            if (Bd >= 1 && BM % Bd == 0 && BCv % Bd == 0 && BCv <= MAX_IMG) {
                B = (int)Bd; C = BCv / Bd; Mn = BM / Bd; ok = true;
            }
        }
        if (!ok) {
            long long num2 = 2 * num;
            if (num2 % out_size == 0) {
                long long Bd = num2 / out_size;
                if (Bd >= 1 && BM % Bd == 0 && BCv % Bd == 0 && BCv <= MAX_IMG) {
                    B = (int)Bd; C = BCv / Bd; Mn = BM / Bd; ok = true;
                }
            }
        }
    }
    int nimg = (int)BCv;
    if (nimg < 1) nimg = 1;
    if (nimg > MAX_IMG) nimg = MAX_IMG;

    bool fast2 = (C == 2) && (B <= 8);

    // Pipeline: fused prep+FFT v (nonzero rows) -> FFT u (Re, dual copies) -> gather
    fft_pass1f<<<nimg*256, 256>>>(fr, fi);
    if (fast2) fft_pass2p<<<nimg*NX, 256>>>();
    else       fft_pass2g<<<nimg*NX, 256>>>((int)C);

    long long out_cap = (long long)out_size;
    int limit = (int)(B * Mn);
    int blocks = (limit + 255) / 256;
    if (fast2) gather2p_kernel<<<blocks, 256>>>(x, out, (int)Mn, limit, out_cap);
    else       gatherN_kernel<<<blocks, 256>>>(x, out, (int)Mn, (int)C, limit, out_cap);
}